// round 17
// baseline (speedup 1.0000x reference)
#include <cuda_runtime.h>
#include <math.h>

#define N_NODES    100000
#define N_EDGES    1600000
#define F_IN       100
#define XV4        (F_IN / 4)          // 25 float4 per x row
#define HEADS      3
#define HEAD_DIM   64
#define HIDDEN     192
#define AXW        (HEADS * F_IN)      // 300 floats per node in g_ax
#define NUM_GRAPHS 128
#define NUM_CLASSES 2
#define NTILE      16
#define N_TILES    (N_NODES / NTILE)   // 6250
#define SCAN_BLK   1024
#define SCAN_NB    ((N_NODES + SCAN_BLK - 1) / SCAN_BLK)   // 98
#define POOL_N     (NUM_GRAPHS * HIDDEN)                   // 24576
#define DEG_BINS   64
#define SORT_BINS  (NUM_GRAPHS * DEG_BINS)                 // 8192

// ---------------- scratch (device globals; no allocations allowed) ----------
__device__ float    g_ax[(size_t)N_NODES * AXW];  // 120 MB aggregated x
__device__ float    g_watt[2 * AXW];              // [src|dst] W@att, 600 floats
__device__ float4   g_as4[N_NODES];               // a_src per node (xyz used)
__device__ float4   g_ad4[N_NODES];               // a_dst per node
__device__ int      g_deg[N_NODES];               // zero-init; re-armed by scan3
__device__ int      g_off[N_NODES + 1];
__device__ int      g_cur[N_NODES];
__device__ int      g_csr[N_EDGES];
__device__ int      g_bsum[SCAN_NB];
__device__ int      g_bpre[SCAN_NB];
__device__ unsigned g_pooled_u[POOL_N];           // ordered-uint encoded max
__device__ int      g_shist[SORT_BINS];           // zero-init; re-armed by scan3
__device__ int      g_scur[SORT_BINS];
__device__ int      g_perm[N_NODES];

// ---------------- helpers ----------------------------------------------------
__device__ __forceinline__ unsigned long long pack2(float lo, float hi) {
    unsigned long long r;
    asm("mov.b64 %0, {%1, %2};" : "=l"(r) : "f"(lo), "f"(hi));
    return r;
}
__device__ __forceinline__ void unpack2(unsigned long long v, float& lo, float& hi) {
    asm("mov.b64 {%0, %1}, %2;" : "=f"(lo), "=f"(hi) : "l"(v));
}
__device__ __forceinline__ void fma2(unsigned long long& acc, unsigned long long a,
                                     unsigned long long b) {
    asm("fma.rn.f32x2 %0, %1, %2, %0;" : "+l"(acc) : "l"(a), "l"(b));
}
__device__ __forceinline__ float lrelu02(float v) { return (v > 0.f) ? v : 0.2f * v; }
__device__ __forceinline__ unsigned fenc(float f) {
    unsigned u = __float_as_uint(f);
    return (u & 0x80000000u) ? ~u : (u | 0x80000000u);
}
__device__ __forceinline__ float fdec(unsigned u) {
    u = (u & 0x80000000u) ? (u & 0x7fffffffu) : ~u;
    return __uint_as_float(u);
}
#define ENC_NEG_INF 0x007fffffu   // fenc(-INFINITY)

// ---------------- 0) wsrc/wdst = W @ att  (tiny) -----------------------------
__global__ void wprep_kernel(const float* __restrict__ W,
                             const float* __restrict__ att_s,
                             const float* __restrict__ att_d) {
    for (int idx = threadIdx.x; idx < 2 * AXW; idx += blockDim.x) {
        int kind = idx / AXW;          // 0 = src, 1 = dst
        int r = idx - kind * AXW;
        int h = r / F_IN, k = r - h * F_IN;
        const float* att = kind ? att_d : att_s;
        float s = 0.f;
        #pragma unroll 4
        for (int d = 0; d < HEAD_DIM; d++)
            s += W[k * HIDDEN + h * HEAD_DIM + d] * att[h * HEAD_DIM + d];
        g_watt[idx] = s;
    }
}

// ---------------- 1) per-node attention logits straight from x ---------------
// one warp per node: 25 lanes hold the 400B x row as float4.
__global__ void __launch_bounds__(256) logit_kernel(const float* __restrict__ x) {
    const int gw = (blockIdx.x * 256 + threadIdx.x) >> 5;
    const int lane = threadIdx.x & 31;
    if (gw >= N_NODES) return;
    const int n = gw;

    float ss0 = 0.f, ss1 = 0.f, ss2 = 0.f, dd0 = 0.f, dd1 = 0.f, dd2 = 0.f;
    if (lane < XV4) {
        const float4 xv = reinterpret_cast<const float4*>(x)[(size_t)n * XV4 + lane];
        const float4* w4 = reinterpret_cast<const float4*>(g_watt);
        float4 w;
        w = w4[0 * XV4 + lane]; ss0 = xv.x * w.x + xv.y * w.y + xv.z * w.z + xv.w * w.w;
        w = w4[1 * XV4 + lane]; ss1 = xv.x * w.x + xv.y * w.y + xv.z * w.z + xv.w * w.w;
        w = w4[2 * XV4 + lane]; ss2 = xv.x * w.x + xv.y * w.y + xv.z * w.z + xv.w * w.w;
        w = w4[3 * XV4 + lane]; dd0 = xv.x * w.x + xv.y * w.y + xv.z * w.z + xv.w * w.w;
        w = w4[4 * XV4 + lane]; dd1 = xv.x * w.x + xv.y * w.y + xv.z * w.z + xv.w * w.w;
        w = w4[5 * XV4 + lane]; dd2 = xv.x * w.x + xv.y * w.y + xv.z * w.z + xv.w * w.w;
    }
    #pragma unroll
    for (int o = 16; o > 0; o >>= 1) {
        ss0 += __shfl_xor_sync(0xffffffffu, ss0, o);
        ss1 += __shfl_xor_sync(0xffffffffu, ss1, o);
        ss2 += __shfl_xor_sync(0xffffffffu, ss2, o);
        dd0 += __shfl_xor_sync(0xffffffffu, dd0, o);
        dd1 += __shfl_xor_sync(0xffffffffu, dd1, o);
        dd2 += __shfl_xor_sync(0xffffffffu, dd2, o);
    }
    if (lane == 0) {
        g_as4[n] = make_float4(ss0, ss1, ss2, 0.f);
        g_ad4[n] = make_float4(dd0, dd1, dd2, 0.f);
    }
}

// ---------------- 2) CSR build (side stream) --------------------------------
__global__ void count_kernel(const int* __restrict__ ei) {
    int e = blockIdx.x * blockDim.x + threadIdx.x;
    if (e < N_EDGES) {
        int dst = ei[N_EDGES + e];
        if ((unsigned)dst < N_NODES) atomicAdd(&g_deg[dst], 1);
    }
}

__global__ void __launch_bounds__(SCAN_BLK) scan1_kernel() {
    __shared__ int wsum[32];
    const int t = threadIdx.x, lane = t & 31, warp = t >> 5;
    int i = blockIdx.x * SCAN_BLK + t;
    int v = (i < N_NODES) ? g_deg[i] : 0;
    int xinc = v;
    #pragma unroll
    for (int o = 1; o < 32; o <<= 1) {
        int y = __shfl_up_sync(0xffffffffu, xinc, o);
        if (lane >= o) xinc += y;
    }
    if (lane == 31) wsum[warp] = xinc;
    __syncthreads();
    if (warp == 0) {
        int s = wsum[lane];
        #pragma unroll
        for (int o = 1; o < 32; o <<= 1) {
            int y = __shfl_up_sync(0xffffffffu, s, o);
            if (lane >= o) s += y;
        }
        wsum[lane] = s;
    }
    __syncthreads();
    int wexcl = (warp == 0) ? 0 : wsum[warp - 1];
    if (i < N_NODES) g_off[i] = wexcl + xinc - v;     // block-local exclusive
    if (t == SCAN_BLK - 1) g_bsum[blockIdx.x] = wexcl + xinc;
}

__global__ void scan2_kernel() {
    __shared__ int wsum[32];
    const int t = threadIdx.x, lane = t & 31, warp = t >> 5;   // 128 threads
    int v = (t < SCAN_NB) ? g_bsum[t] : 0;
    int xinc = v;
    #pragma unroll
    for (int o = 1; o < 32; o <<= 1) {
        int y = __shfl_up_sync(0xffffffffu, xinc, o);
        if (lane >= o) xinc += y;
    }
    if (lane == 31) wsum[warp] = xinc;
    __syncthreads();
    if (warp == 0 && lane < 4) {
        int s = wsum[lane];
        for (int o = 1; o < 4; o <<= 1) {
            int y = __shfl_up_sync(0xfu, s, o);
            if (lane >= o) s += y;
        }
        wsum[lane] = s;
    }
    __syncthreads();
    int wexcl = (warp == 0) ? 0 : wsum[warp - 1];
    if (t < SCAN_NB) g_bpre[t] = wexcl + xinc - v;
    if (t == 0) g_off[N_NODES] = N_EDGES;
}

__global__ void __launch_bounds__(SCAN_BLK) scan3_kernel() {
    int i = blockIdx.x * SCAN_BLK + threadIdx.x;
    if (i < N_NODES) {
        int o = g_off[i] + g_bpre[blockIdx.x];
        g_off[i] = o;
        g_cur[i] = o;
        g_deg[i] = 0;          // re-arm degree histogram for the next replay
    }
    if (i < POOL_N) g_pooled_u[i] = ENC_NEG_INF;
    if (i < SORT_BINS) g_shist[i] = 0;   // re-arm sort histogram
}

// ---------------- 2b) degree-bucketed permutation (side stream) -------------
__global__ void sort_hist_kernel(const int* __restrict__ batch) {
    int i = blockIdx.x * blockDim.x + threadIdx.x;
    if (i < N_NODES) {
        int deg = g_off[i + 1] - g_off[i];
        int b = batch[i];
        int bin = b * DEG_BINS + min(deg, DEG_BINS - 1);
        atomicAdd(&g_shist[bin], 1);
    }
}

__global__ void __launch_bounds__(SCAN_BLK) sort_scan_kernel() {
    __shared__ int wsum[32];
    const int t = threadIdx.x, lane = t & 31, warp = t >> 5;
    int carry = 0;
    #pragma unroll
    for (int it = 0; it < SORT_BINS / SCAN_BLK; it++) {   // 8 chunks
        int i = it * SCAN_BLK + t;
        int v = g_shist[i];
        int xinc = v;
        #pragma unroll
        for (int o = 1; o < 32; o <<= 1) {
            int y = __shfl_up_sync(0xffffffffu, xinc, o);
            if (lane >= o) xinc += y;
        }
        if (lane == 31) wsum[warp] = xinc;
        __syncthreads();
        if (warp == 0) {
            int s = wsum[lane];
            #pragma unroll
            for (int o = 1; o < 32; o <<= 1) {
                int y = __shfl_up_sync(0xffffffffu, s, o);
                if (lane >= o) s += y;
            }
            wsum[lane] = s;
        }
        __syncthreads();
        int wexcl = (warp == 0) ? 0 : wsum[warp - 1];
        g_scur[i] = carry + wexcl + xinc - v;
        carry += wsum[31];
        __syncthreads();
    }
}

__global__ void sort_scatter_kernel(const int* __restrict__ batch) {
    int i = blockIdx.x * blockDim.x + threadIdx.x;
    if (i < N_NODES) {
        int deg = g_off[i + 1] - g_off[i];
        int b = batch[i];
        int bin = b * DEG_BINS + min(deg, DEG_BINS - 1);
        int pos = atomicAdd(&g_scur[bin], 1);
        g_perm[pos] = i;
    }
}

__global__ void fill_kernel(const int* __restrict__ ei) {
    int e = blockIdx.x * blockDim.x + threadIdx.x;
    if (e < N_EDGES) {
        int src = ei[e];
        int dst = ei[N_EDGES + e];
        if ((unsigned)dst < N_NODES) {
            int pos = atomicAdd(&g_cur[dst], 1);
            g_csr[pos] = src;
        }
    }
}

// ---------------- 3) aggregation in x-space ----------------------------------
// one warp per destination; 25 lanes gather the 400B x row as ONE float4 per
// edge; 3 per-head float4 accumulators; x2-unrolled broadcast loop.
__global__ void __launch_bounds__(256) agg_kernel(const float* __restrict__ x) {
    const int wid = threadIdx.x >> 5, lane = threadIdx.x & 31;
    const int slot = blockIdx.x * 8 + wid;
    if (slot >= N_NODES) return;
    const int n = g_perm[slot];

    const float4 ad4 = g_ad4[n];
    const float4 asn = g_as4[n];
    const float ps0 = __expf(lrelu02(asn.x + ad4.x));
    const float ps1 = __expf(lrelu02(asn.y + ad4.y));
    const float ps2 = __expf(lrelu02(asn.z + ad4.z));
    const int beg = g_off[n];
    const int cnt_e = g_off[n + 1] - beg;
    const int total = cnt_e + 1;                 // + self loop

    float d0 = 0.f, d1 = 0.f, d2 = 0.f;
    float4 A0 = {0.f,0.f,0.f,0.f}, A1 = {0.f,0.f,0.f,0.f}, A2 = {0.f,0.f,0.f,0.f};
    const float4* x4 = reinterpret_cast<const float4*>(x);

    for (int base = 0; base < total; base += 32) {
        int idx = base + lane;
        int src = n;
        float p0 = 0.f, p1 = 0.f, p2 = 0.f;
        if (idx < cnt_e) {
            src = g_csr[beg + idx];
            float4 s4 = g_as4[src];
            p0 = __expf(lrelu02(s4.x + ad4.x));
            p1 = __expf(lrelu02(s4.y + ad4.y));
            p2 = __expf(lrelu02(s4.z + ad4.z));
        } else if (idx == cnt_e) {
            p0 = ps0; p1 = ps1; p2 = ps2;
        }
        d0 += p0; d1 += p1; d2 += p2;

        const int lim = min(32, total - base);
        int kk = 0;
        for (; kk + 2 <= lim; kk += 2) {
            int sA = __shfl_sync(0xffffffffu, src, kk);
            int sB = __shfl_sync(0xffffffffu, src, kk + 1);
            float qA0 = __shfl_sync(0xffffffffu, p0, kk);
            float qA1 = __shfl_sync(0xffffffffu, p1, kk);
            float qA2 = __shfl_sync(0xffffffffu, p2, kk);
            float qB0 = __shfl_sync(0xffffffffu, p0, kk + 1);
            float qB1 = __shfl_sync(0xffffffffu, p1, kk + 1);
            float qB2 = __shfl_sync(0xffffffffu, p2, kk + 1);
            if (lane < XV4) {
                float4 vA = x4[(size_t)sA * XV4 + lane];
                float4 vB = x4[(size_t)sB * XV4 + lane];
                A0.x += qA0 * vA.x + qB0 * vB.x;
                A0.y += qA0 * vA.y + qB0 * vB.y;
                A0.z += qA0 * vA.z + qB0 * vB.z;
                A0.w += qA0 * vA.w + qB0 * vB.w;
                A1.x += qA1 * vA.x + qB1 * vB.x;
                A1.y += qA1 * vA.y + qB1 * vB.y;
                A1.z += qA1 * vA.z + qB1 * vB.z;
                A1.w += qA1 * vA.w + qB1 * vB.w;
                A2.x += qA2 * vA.x + qB2 * vB.x;
                A2.y += qA2 * vA.y + qB2 * vB.y;
                A2.z += qA2 * vA.z + qB2 * vB.z;
                A2.w += qA2 * vA.w + qB2 * vB.w;
            }
        }
        if (kk < lim) {
            int s = __shfl_sync(0xffffffffu, src, kk);
            float q0 = __shfl_sync(0xffffffffu, p0, kk);
            float q1 = __shfl_sync(0xffffffffu, p1, kk);
            float q2 = __shfl_sync(0xffffffffu, p2, kk);
            if (lane < XV4) {
                float4 v = x4[(size_t)s * XV4 + lane];
                A0.x += q0 * v.x; A0.y += q0 * v.y; A0.z += q0 * v.z; A0.w += q0 * v.w;
                A1.x += q1 * v.x; A1.y += q1 * v.y; A1.z += q1 * v.z; A1.w += q1 * v.w;
                A2.x += q2 * v.x; A2.y += q2 * v.y; A2.z += q2 * v.z; A2.w += q2 * v.w;
            }
        }
    }

    #pragma unroll
    for (int o = 16; o > 0; o >>= 1) {
        d0 += __shfl_xor_sync(0xffffffffu, d0, o);
        d1 += __shfl_xor_sync(0xffffffffu, d1, o);
        d2 += __shfl_xor_sync(0xffffffffu, d2, o);
    }
    const float i0 = 1.f / d0, i1 = 1.f / d1, i2 = 1.f / d2;

    if (lane < XV4) {
        float* axp = g_ax + (size_t)n * AXW;
        float4 o0 = make_float4(A0.x * i0, A0.y * i0, A0.z * i0, A0.w * i0);
        float4 o1 = make_float4(A1.x * i1, A1.y * i1, A1.z * i1, A1.w * i1);
        float4 o2 = make_float4(A2.x * i2, A2.y * i2, A2.z * i2, A2.w * i2);
        reinterpret_cast<float4*>(axp)[lane] = o0;
        reinterpret_cast<float4*>(axp + F_IN)[lane] = o1;
        reinterpret_cast<float4*>(axp + 2 * F_IN)[lane] = o2;
    }
}

// ---------------- 4) post-GEMM: out = ax@W + bias, lrelu, fused max-pool ----
// Same NTILE=16 hot loop as the proven gemm; thread t = column, head = t/64.
__global__ void __launch_bounds__(192) postgemm_kernel(
    const float* __restrict__ W, const float* __restrict__ bias,
    const int* __restrict__ batch) {
    __shared__ __align__(16) float xs2[HEADS * F_IN * NTILE];   // [h][k][j] 19.2 KB
    __shared__ int sb[NTILE];
    const int t = threadIdx.x;
    const int H = t >> 6;                  // head (warp-pair uniform)
    const float bt = bias[t];

    for (int tile = blockIdx.x; tile < N_TILES; tile += gridDim.x) {
        const int n0 = tile * NTILE;
        for (int idx = t; idx < AXW * NTILE; idx += 192) {
            int j = idx / AXW, r = idx - j * AXW;
            int h = r / F_IN, k = r - h * F_IN;
            xs2[(h * F_IN + k) * NTILE + j] = g_ax[(size_t)(n0 + j) * AXW + r];
        }
        if (t < NTILE) sb[t] = batch[n0 + t];
        __syncthreads();

        unsigned long long a0 = 0ull, a1 = 0ull, a2 = 0ull, a3 = 0ull;
        unsigned long long a4 = 0ull, a5 = 0ull, a6 = 0ull, a7 = 0ull;
        #pragma unroll 4
        for (int k = 0; k < F_IN; k++) {
            float w = W[k * HIDDEN + t];
            unsigned long long ww = pack2(w, w);
            const ulonglong2* xv = reinterpret_cast<const ulonglong2*>(
                &xs2[(H * F_IN + k) * NTILE]);
            ulonglong2 xab = xv[0];
            ulonglong2 xcd = xv[1];
            ulonglong2 xef = xv[2];
            ulonglong2 xgh = xv[3];
            fma2(a0, xab.x, ww);
            fma2(a1, xab.y, ww);
            fma2(a2, xcd.x, ww);
            fma2(a3, xcd.y, ww);
            fma2(a4, xef.x, ww);
            fma2(a5, xef.y, ww);
            fma2(a6, xgh.x, ww);
            fma2(a7, xgh.y, ww);
        }
        float hv[NTILE];
        unpack2(a0, hv[0],  hv[1]);
        unpack2(a1, hv[2],  hv[3]);
        unpack2(a2, hv[4],  hv[5]);
        unpack2(a3, hv[6],  hv[7]);
        unpack2(a4, hv[8],  hv[9]);
        unpack2(a5, hv[10], hv[11]);
        unpack2(a6, hv[12], hv[13]);
        unpack2(a7, hv[14], hv[15]);

        // bias + leaky_relu(0.01) + run-wise max-pool over the 16 tile nodes
        float cur = -INFINITY;
        int curg = -2;
        #pragma unroll
        for (int j = 0; j < NTILE; j++) {
            float v = hv[j] + bt;
            v = (v > 0.f) ? v : 0.01f * v;
            int g = sb[j];
            if (g != curg) {
                if (curg >= 0)
                    atomicMax(&g_pooled_u[curg * HIDDEN + t], fenc(cur));
                curg = g;
                cur = -INFINITY;
            }
            cur = fmaxf(cur, v);
        }
        if (curg >= 0)
            atomicMax(&g_pooled_u[curg * HIDDEN + t], fenc(cur));
        __syncthreads();
    }
}

// ---------------- 5) classifier (warp per output) ----------------------------
__global__ void __launch_bounds__(256) cls_kernel(const float* __restrict__ cw,
                                                  const float* __restrict__ cb,
                                                  float* __restrict__ out) {
    const int w = (blockIdx.x * 256 + threadIdx.x) >> 5;   // 0..255
    const int lane = threadIdx.x & 31;
    if (w >= NUM_GRAPHS * NUM_CLASSES) return;
    const int g = w >> 1, c = w & 1;
    float s = 0.f;
    #pragma unroll
    for (int i = 0; i < HIDDEN / 32; i++) {
        int k = lane + 32 * i;
        s += fdec(g_pooled_u[g * HIDDEN + k]) * cw[k * NUM_CLASSES + c];
    }
    #pragma unroll
    for (int o = 16; o > 0; o >>= 1)
        s += __shfl_xor_sync(0xffffffffu, s, o);
    if (lane == 0) out[g * NUM_CLASSES + c] = s + cb[c];
}

// ---------------- launch ------------------------------------------------------
extern "C" void kernel_launch(void* const* d_in, const int* in_sizes, int n_in,
                              void* d_out, int out_size) {
    const float* x     = (const float*)d_in[0];
    const int*   ei    = (const int*)d_in[1];
    const int*   batch = (const int*)d_in[2];
    const float* W     = (const float*)d_in[3];
    const float* att_s = (const float*)d_in[4];
    const float* att_d = (const float*)d_in[5];
    const float* bias  = (const float*)d_in[6];
    const float* cw    = (const float*)d_in[7];
    const float* cb    = (const float*)d_in[8];
    float* out = (float*)d_out;

    cudaStream_t s2;
    cudaStreamCreateWithFlags(&s2, cudaStreamNonBlocking);
    cudaEvent_t evFork, evJoin;
    cudaEventCreateWithFlags(&evFork, cudaEventDisableTiming);
    cudaEventCreateWithFlags(&evJoin, cudaEventDisableTiming);

    cudaEventRecord(evFork, 0);
    cudaStreamWaitEvent(s2, evFork, 0);

    // side stream: CSR build + degree-bucketed permutation
    count_kernel<<<(N_EDGES + 255) / 256, 256, 0, s2>>>(ei);
    scan1_kernel<<<SCAN_NB, SCAN_BLK, 0, s2>>>();
    scan2_kernel<<<1, 128, 0, s2>>>();
    scan3_kernel<<<SCAN_NB, SCAN_BLK, 0, s2>>>();
    sort_hist_kernel<<<(N_NODES + 255) / 256, 256, 0, s2>>>(batch);
    sort_scan_kernel<<<1, SCAN_BLK, 0, s2>>>();
    sort_scatter_kernel<<<(N_NODES + 255) / 256, 256, 0, s2>>>(batch);
    fill_kernel<<<(N_EDGES + 255) / 256, 256, 0, s2>>>(ei);
    cudaEventRecord(evJoin, s2);

    // main stream: logits from x (runs alongside CSR chain)
    wprep_kernel<<<1, 192>>>(W, att_s, att_d);
    logit_kernel<<<(N_NODES + 7) / 8, 256>>>(x);

    // join, then aggregation in x-space, post-GEMM + pool, classifier
    cudaStreamWaitEvent(0, evJoin, 0);
    agg_kernel<<<(N_NODES + 7) / 8, 256>>>(x);
    postgemm_kernel<<<1480, 192>>>(W, bias, batch);
    cls_kernel<<<32, 256>>>(cw, cb, out);

    cudaEventDestroy(evFork);
    cudaEventDestroy(evJoin);
    cudaStreamDestroy(s2);
}